// round 16
// baseline (speedup 1.0000x reference)
#include <cuda_runtime.h>
#include <cstdint>

#define NB1 64
#define NS1 128
#define NB2 64
#define NS2 128
#define NH  768

// Normalized (and tf32-RNA-rounded) inputs
__device__ float g_x1n[NB1 * NS1 * NH];
__device__ float g_x2n[NB2 * NS2 * NH];

// ---------------------------------------------------------------------------
// Kernel 1: L2-normalize rows, round to tf32 (RNA) so HW tf32 MMA is exact.
// ---------------------------------------------------------------------------
__global__ void normalize_kernel(const float* __restrict__ x1,
                                 const float* __restrict__ x2) {
    const int row = blockIdx.x;
    const float* src = (blockIdx.y == 0) ? x1 : x2;
    float* dst       = (blockIdx.y == 0) ? g_x1n : g_x2n;

    const float* p = src + (size_t)row * NH;
    float v[3];
    float s = 0.f;
#pragma unroll
    for (int i = 0; i < 3; i++) {
        v[i] = p[threadIdx.x + i * 256];
        s += v[i] * v[i];
    }
#pragma unroll
    for (int o = 16; o > 0; o >>= 1) s += __shfl_xor_sync(0xffffffffu, s, o);
    __shared__ float red[8];
    if ((threadIdx.x & 31) == 0) red[threadIdx.x >> 5] = s;
    __syncthreads();
    float tot = 0.f;
#pragma unroll
    for (int i = 0; i < 8; i++) tot += red[i];
    const float inv = rsqrtf(tot);

    float* d = dst + (size_t)row * NH;
#pragma unroll
    for (int i = 0; i < 3; i++) {
        float w = v[i] * inv;
        uint32_t r;
        asm("cvt.rna.tf32.f32 %0, %1;" : "=r"(r) : "f"(w));
        d[threadIdx.x + i * 256] = __uint_as_float(r);
    }
}

// ---------------------------------------------------------------------------
// Kernel 2: one CTA per (a,b) pair. Warp-level tf32 mma.sync GEMM + fused
// masked row/col max + masked means.
// R16: 3-stage cp.async pipeline, ONE __syncthreads per tile
//   loop body: wait(tile t) -> sync -> issue(tile t+2) -> compute(tile t)
//   The sync proves all warps finished tile t-1 before its stage
//   ((t+2)%3 == (t-1)%3) is overwritten. Prefetch distance = 2 tiles.
// ---------------------------------------------------------------------------
#define KT 32
#define NTILES (NH / KT)  // 24
#define PADF 36
#define MAT_BYTES (128 * PADF * 4)      // 18432 per matrix per stage
#define STAGE_BYTES (2 * MAT_BYTES)     // A+B per stage = 36864
#define OFF_AUX (3 * STAGE_BYTES)       // 110592
#define DSMEM_TOTAL (OFF_AUX + 2304)    // aux: 4x512 masks + rbuf + pad

__device__ __forceinline__ uint32_t smem_u32(const void* p) {
    uint32_t a;
    asm("{ .reg .u64 t; cvta.to.shared.u64 t, %1; cvt.u32.u64 %0, t; }"
        : "=r"(a) : "l"(p));
    return a;
}
__device__ __forceinline__ void cp16(uint32_t dst, const void* src) {
    asm volatile("cp.async.cg.shared.global [%0], [%1], 16;"
                 :: "r"(dst), "l"(src) : "memory");
}
__device__ __forceinline__ void cp_commit() {
    asm volatile("cp.async.commit_group;" ::: "memory");
}
template <int N>
__device__ __forceinline__ void cp_wait() {
    asm volatile("cp.async.wait_group %0;" :: "n"(N) : "memory");
}

__device__ __forceinline__ void mma_tf32(float* d, uint32_t a0, uint32_t a1,
                                         uint32_t a2, uint32_t a3,
                                         uint32_t b0, uint32_t b1) {
    asm volatile(
        "mma.sync.aligned.m16n8k8.row.col.f32.tf32.tf32.f32 "
        "{%0,%1,%2,%3}, {%4,%5,%6,%7}, {%8,%9}, {%0,%1,%2,%3};"
        : "+f"(d[0]), "+f"(d[1]), "+f"(d[2]), "+f"(d[3])
        : "r"(a0), "r"(a1), "r"(a2), "r"(a3), "r"(b0), "r"(b1));
}

__device__ __forceinline__ float shfl_max(float v, int mask) {
    return fmaxf(v, __shfl_xor_sync(0xffffffffu, v, mask));
}

__global__ __launch_bounds__(256, 2)
void pair_kernel(const int* __restrict__ mask1,
                 const int* __restrict__ mask2,
                 float* __restrict__ out) {
    extern __shared__ __align__(16) char dsm[];
    const int a = blockIdx.x;
    const int b = blockIdx.y;
    const int tid = threadIdx.x;
    const int lane = tid & 31;
    const int warp = tid >> 5;
    const int wr = warp >> 2;       // 0..1  : 64-row block
    const int wc = warp & 3;        // 0..3  : 32-col block
    const int g = lane >> 2;        // groupID 0..7
    const int tg = lane & 3;        // threadID-in-group 0..3

    const uint32_t smem_base = smem_u32(dsm);

    // aux region (persists through GEMM)
    float* m1raw = (float*)(dsm + OFF_AUX);
    float* m2raw = (float*)(dsm + OFF_AUX + 512);
    float* m1b   = (float*)(dsm + OFF_AUX + 1024);
    float* m2b   = (float*)(dsm + OFF_AUX + 1536);
    float* rbuf  = (float*)(dsm + OFF_AUX + 2048);
    // epilogue scratch aliases stage 0 (last GEMM use: tile 21; tail tiles
    // 22, 23 live in stages 1, 2 -> disjoint from bytes [0, 3072))
    float* rowp = (float*)dsm;            // [128][4]
    float* colp = (float*)(dsm + 2048);   // [128][2]

    // masks: raw 0/1 + additive bias form
    if (tid < 128) {
        const float m = (float)mask1[a * NS1 + tid];
        m1raw[tid] = m;
        m1b[tid] = (m != 0.f) ? 0.f : -2e30f;
    } else {
        const int r = tid - 128;
        const float m = (float)mask2[b * NS2 + r];
        m2raw[r] = m;
        m2b[r] = (m != 0.f) ? 0.f : -2e30f;
    }

    const float* Abase = g_x1n + (size_t)a * NS1 * NH;
    const float* Bbase = g_x2n + (size_t)b * NS2 * NH;

    float acc[4][4][4];
#pragma unroll
    for (int i = 0; i < 4; i++)
#pragma unroll
        for (int j = 0; j < 4; j++)
#pragma unroll
            for (int q = 0; q < 4; q++) acc[i][j][q] = 0.f;

    const int lm = tid >> 3;  // 0..31 : row within 32-row pass
    const int lk = tid & 7;   // 0..7  : 16B segment within 32-float k-tile

    // prologue: tiles 0 and 1 into stages 0 and 1 (two groups in flight)
#pragma unroll
    for (int pt = 0; pt < 2; pt++) {
        const uint32_t bA = smem_base + (uint32_t)pt * STAGE_BYTES;
        const uint32_t bB = bA + MAT_BYTES;
        const int k0 = pt * KT;
#pragma unroll
        for (int p = 0; p < 4; p++) {
            const int m = lm + 32 * p;
            const uint32_t so = (uint32_t)(m * PADF + lk * 4) * 4u;
            cp16(bA + so, Abase + (size_t)m * NH + k0 + lk * 4);
            cp16(bB + so, Bbase + (size_t)m * NH + k0 + lk * 4);
        }
        cp_commit();
    }

    for (int t = 0; t < NTILES; t++) {
        // tile t resident (t+1 may stay in flight)
        if (t + 1 < NTILES) cp_wait<1>(); else cp_wait<0>();
        __syncthreads();   // tile t visible; all warps done with tile t-1

        // issue tile t+2 into stage (t+2)%3 == (t-1)%3 (readers all done)
        if (t + 2 < NTILES) {
            const int st = (t + 2) % 3;
            const uint32_t bA = smem_base + (uint32_t)st * STAGE_BYTES;
            const uint32_t bB = bA + MAT_BYTES;
            const int k0 = (t + 2) * KT;
#pragma unroll
            for (int p = 0; p < 4; p++) {
                const int m = lm + 32 * p;
                const uint32_t so = (uint32_t)(m * PADF + lk * 4) * 4u;
                cp16(bA + so, Abase + (size_t)m * NH + k0 + lk * 4);
                cp16(bB + so, Bbase + (size_t)m * NH + k0 + lk * 4);
            }
            cp_commit();
        }

        const float* As = (const float*)(dsm + (t % 3) * STAGE_BYTES);
        const float* Bs = As + 128 * PADF;

#pragma unroll
        for (int ks = 0; ks < KT; ks += 8) {
            uint32_t bf[4][2];
#pragma unroll
            for (int j = 0; j < 4; j++) {
                const float* bp = &Bs[(wc * 32 + j * 8 + g) * PADF + ks + tg];
                bf[j][0] = __float_as_uint(bp[0]);
                bf[j][1] = __float_as_uint(bp[4]);
            }
#pragma unroll
            for (int i = 0; i < 4; i++) {
                const float* ap0 = &As[(wr * 64 + i * 16 + g) * PADF + ks + tg];
                const float* ap1 = ap0 + 8 * PADF;
                const uint32_t a0 = __float_as_uint(ap0[0]);
                const uint32_t a1 = __float_as_uint(ap1[0]);
                const uint32_t a2 = __float_as_uint(ap0[4]);
                const uint32_t a3 = __float_as_uint(ap1[4]);
#pragma unroll
                for (int j = 0; j < 4; j++)
                    mma_tf32(acc[i][j], a0, a1, a2, a3, bf[j][0], bf[j][1]);
            }
        }
        // no trailing sync: next iteration's sync protects stage reuse
    }

    // ---- fused masked row-max (over cols, bias m2b) ----
    // D frag mapping: d0:(g, 2tg) d1:(g, 2tg+1) d2:(g+8, 2tg) d3:(g+8, 2tg+1)
#pragma unroll
    for (int i = 0; i < 4; i++) {
        float r0 = -3e30f, r1 = -3e30f;
#pragma unroll
        for (int j = 0; j < 4; j++) {
            const int c0 = wc * 32 + j * 8 + 2 * tg;
            const float b0 = m2b[c0], b1 = m2b[c0 + 1];
            r0 = fmaxf(r0, fmaxf(acc[i][j][0] + b0, acc[i][j][1] + b1));
            r1 = fmaxf(r1, fmaxf(acc[i][j][2] + b0, acc[i][j][3] + b1));
        }
        r0 = shfl_max(shfl_max(r0, 1), 2);  // reduce over tg lanes
        r1 = shfl_max(shfl_max(r1, 1), 2);
        if (tg == 0) {
            rowp[(wr * 64 + i * 16 + g) * 4 + wc] = r0;
            rowp[(wr * 64 + i * 16 + g + 8) * 4 + wc] = r1;
        }
    }

    // ---- fused masked col-max (over rows, bias m1b) ----
#pragma unroll
    for (int j = 0; j < 4; j++) {
        float c0m = -3e30f, c1m = -3e30f;
#pragma unroll
        for (int i = 0; i < 4; i++) {
            const int r0i = wr * 64 + i * 16 + g;
            const float bb0 = m1b[r0i], bb1 = m1b[r0i + 8];
            c0m = fmaxf(c0m, fmaxf(acc[i][j][0] + bb0, acc[i][j][2] + bb1));
            c1m = fmaxf(c1m, fmaxf(acc[i][j][1] + bb0, acc[i][j][3] + bb1));
        }
        c0m = shfl_max(shfl_max(shfl_max(c0m, 4), 8), 16);  // reduce over g
        c1m = shfl_max(shfl_max(shfl_max(c1m, 4), 8), 16);
        if (g == 0) {
            colp[(wc * 32 + j * 8 + 2 * tg) * 2 + wr] = c0m;
            colp[(wc * 32 + j * 8 + 2 * tg + 1) * 2 + wr] = c1m;
        }
    }
    __syncthreads();

    // ---- finish maxes, masked mean contributions ----
    float val;
    {
        const int r = tid & 127;
        float mx;
        const float* mv;
        if (tid < 128) {
            mx = fmaxf(fmaxf(rowp[r * 4 + 0], rowp[r * 4 + 1]),
                       fmaxf(rowp[r * 4 + 2], rowp[r * 4 + 3]));
            mv = m1raw;
        } else {
            mx = fmaxf(colp[r * 2 + 0], colp[r * 2 + 1]);
            mv = m2raw;
        }
        float cnt = 0.f;
#pragma unroll 8
        for (int q = 0; q < 128; q++) cnt += mv[q];
        val = mv[r] * (mx / cnt) * 0.5f;
    }

#pragma unroll
    for (int o = 16; o > 0; o >>= 1) val += __shfl_xor_sync(0xffffffffu, val, o);
    if ((tid & 31) == 0) rbuf[tid >> 5] = val;
    __syncthreads();
    if (tid == 0) {
        float s = 0.f;
#pragma unroll
        for (int i = 0; i < 8; i++) s += rbuf[i];
        out[a * NB2 + b] = s;
    }
}

// ---------------------------------------------------------------------------
extern "C" void kernel_launch(void* const* d_in, const int* in_sizes, int n_in,
                              void* d_out, int out_size) {
    const float* x1 = (const float*)d_in[0];
    const int* mask1 = (const int*)d_in[1];
    const float* x2 = (const float*)d_in[2];
    const int* mask2 = (const int*)d_in[3];
    float* out = (float*)d_out;

    cudaFuncSetAttribute(pair_kernel,
                         cudaFuncAttributeMaxDynamicSharedMemorySize,
                         DSMEM_TOTAL);

    normalize_kernel<<<dim3(NB1 * NS1, 2), 256>>>(x1, x2);
    pair_kernel<<<dim3(NB1, NB2), 256, DSMEM_TOTAL>>>(mask1, mask2, out);
}